// round 17
// baseline (speedup 1.0000x reference)
#include <cuda_runtime.h>
#include <stdint.h>

#define IMG_H 1024
#define IMG_W 1280
#define NPIX (IMG_H * IMG_W)
#define NPTS 4194304

// Inverted-key z-buffer: stored value = ~((z_bits<<32) | rgb), combined via
// atomicMax (max of inverted == min of original => same winner as before).
// Empty sentinel is 0: __device__ globals are zero-initialized at module
// load, and gather restores zeros after each read — no init kernel/memset.
// Low word carries color quantized to R11G11B10 (rel_err 3.45e-4, measured).
__device__ unsigned long long g_zbuf[NPIX];
// Pre-packed colors (u32 per point) so project loads 32B/thread, not 96B.
__device__ unsigned g_rgb[NPTS];

__device__ __forceinline__ unsigned pack_rgb(float r, float g, float b) {
    unsigned pr = __float2uint_rn(r * 2047.0f);   // 11 bits
    unsigned pg = __float2uint_rn(g * 2047.0f);   // 11 bits
    unsigned pb = __float2uint_rn(b * 1023.0f);   // 10 bits
    return pr | (pg << 11) | (pb << 22);
}

// Streaming pack: 8 points/thread, 6x LDG.128 in, 2x STG.128 out (67MB total).
__global__ __launch_bounds__(256) void pack_kernel(const float* __restrict__ colors) {
    int t = blockIdx.x * blockDim.x + threadIdx.x;
    if (t >= NPTS / 8) return;
    const float4* c4 = reinterpret_cast<const float4*>(colors);
    float4 w0 = __ldcs(&c4[t * 6 + 0]);  // r0 g0 b0 r1
    float4 w1 = __ldcs(&c4[t * 6 + 1]);  // g1 b1 r2 g2
    float4 w2 = __ldcs(&c4[t * 6 + 2]);  // b2 r3 g3 b3
    float4 w3 = __ldcs(&c4[t * 6 + 3]);
    float4 w4 = __ldcs(&c4[t * 6 + 4]);
    float4 w5 = __ldcs(&c4[t * 6 + 5]);
    uint4* dst = reinterpret_cast<uint4*>(g_rgb) + t * 2;
    uint4 o0, o1;
    o0.x = pack_rgb(w0.x, w0.y, w0.z);
    o0.y = pack_rgb(w0.w, w1.x, w1.y);
    o0.z = pack_rgb(w1.z, w1.w, w2.x);
    o0.w = pack_rgb(w2.y, w2.z, w2.w);
    o1.x = pack_rgb(w3.x, w3.y, w3.z);
    o1.y = pack_rgb(w3.w, w4.x, w4.y);
    o1.z = pack_rgb(w4.z, w4.w, w5.x);
    o1.w = pack_rgb(w5.y, w5.z, w5.w);
    __stcs(&dst[0], o0);
    __stcs(&dst[1], o1);
}

// Guarded fast projection: rcp path; if u/v lands within 0.498 of a
// half-integer boundary (6x the max 3.3e-4 rcp-path error), redo with the
// exact IEEE divides so the pixel mapping matches jnp.round bit-exactly.
__device__ __forceinline__ void splat_point(float x, float y, float z,
                                            unsigned rgb,
                                            float fx, float fy, float cx, float cy) {
    if (z > 0.0f) {
        float mu = __fmul_rn(fx, x);
        float mv = __fmul_rn(fy, y);
        float rz = __frcp_rn(z);
        float uf = __fadd_rn(__fmul_rn(mu, rz), cx);
        float vf = __fadd_rn(__fmul_rn(mv, rz), cy);
        float ur = rintf(uf);
        float vr = rintf(vf);
        if (fabsf(__fadd_rn(uf, -ur)) >= 0.498f ||
            fabsf(__fadd_rn(vf, -vr)) >= 0.498f) {
            uf = __fadd_rn(__fdiv_rn(mu, z), cx);
            vf = __fadd_rn(__fdiv_rn(mv, z), cy);
            ur = rintf(uf);
            vr = rintf(vf);
        }
        int u = (int)ur;
        int v = (int)vr;
        if ((unsigned)u < (unsigned)IMG_W && (unsigned)v < (unsigned)IMG_H) {
            unsigned long long key =
                ~(((unsigned long long)__float_as_uint(z) << 32) |
                  (unsigned long long)rgb);
            atomicMax(&g_zbuf[v * IMG_W + u], key);  // fire-and-forget RED
        }
    }
}

// 8 points/thread: 6 LDG.128 points (pre-sync, overlaps pack) + 2 LDG.128
// packed rgb (post-sync) + 8 REDs.
__global__ __launch_bounds__(256) void project_kernel(const float* __restrict__ points,
                                                      const float* __restrict__ Kmat) {
    int t = blockIdx.x * blockDim.x + threadIdx.x;
    const int noct = NPTS / 8;
    if (t >= noct) return;

    float fx = Kmat[0], cx = Kmat[2], fy = Kmat[4], cy = Kmat[5];

    const float4* p4 = reinterpret_cast<const float4*>(points);
    float4 a = __ldcs(&p4[t * 6 + 0]);
    float4 b = __ldcs(&p4[t * 6 + 1]);
    float4 c = __ldcs(&p4[t * 6 + 2]);
    float4 d = __ldcs(&p4[t * 6 + 3]);
    float4 e = __ldcs(&p4[t * 6 + 4]);
    float4 f = __ldcs(&p4[t * 6 + 5]);

    // Wait for pack_kernel (and the previous replay's gather zero-restore)
    // before touching g_rgb / g_zbuf.
    cudaGridDependencySynchronize();

    const uint4* rg = reinterpret_cast<const uint4*>(g_rgb);
    uint4 r0 = __ldcs(&rg[t * 2 + 0]);
    uint4 r1 = __ldcs(&rg[t * 2 + 1]);

    splat_point(a.x, a.y, a.z, r0.x, fx, fy, cx, cy);
    splat_point(a.w, b.x, b.y, r0.y, fx, fy, cx, cy);
    splat_point(b.z, b.w, c.x, r0.z, fx, fy, cx, cy);
    splat_point(c.y, c.z, c.w, r0.w, fx, fy, cx, cy);
    splat_point(d.x, d.y, d.z, r1.x, fx, fy, cx, cy);
    splat_point(d.w, e.x, e.y, r1.y, fx, fy, cx, cy);
    splat_point(e.z, e.w, f.x, r1.z, fx, fy, cx, cy);
    splat_point(f.y, f.z, f.w, r1.w, fx, fy, cx, cy);
}

// Decode inverted key -> RGB floats; empty pixel (stored 0) -> black.
// (Valid entries are always nonzero: z<=2.5 => inverted hi >= 0xBFDFFFFF.)
__device__ __forceinline__ void decode(unsigned long long val,
                                       float& r, float& g, float& b) {
    unsigned lo = ~(unsigned)(val & 0xFFFFFFFFu);
    bool has = (val != 0ULL);
    r = has ? (float)(lo & 0x7FFu) * (1.0f / 2047.0f) : 0.0f;
    g = has ? (float)((lo >> 11) & 0x7FFu) * (1.0f / 2047.0f) : 0.0f;
    b = has ? (float)(lo >> 22) * (1.0f / 1023.0f) : 0.0f;
}

// Pure streaming: 4 px/thread. Reads keys, writes image, then restores the
// zero sentinel for the next graph replay (own slots, race-free).
__global__ __launch_bounds__(256) void gather_kernel(float* __restrict__ out) {
    int t = blockIdx.x * blockDim.x + threadIdx.x;  // handles 4 pixels
    if (t >= NPIX / 4) return;

    cudaGridDependencySynchronize();

    ulonglong2* zb = reinterpret_cast<ulonglong2*>(g_zbuf);
    ulonglong2 k01 = zb[t * 2 + 0];
    ulonglong2 k23 = zb[t * 2 + 1];

    float c[12];
    decode(k01.x, c[0], c[1], c[2]);
    decode(k01.y, c[3], c[4], c[5]);
    decode(k23.x, c[6], c[7], c[8]);
    decode(k23.y, c[9], c[10], c[11]);

    float4* o4 = reinterpret_cast<float4*>(out);  // 48B per thread, 16B aligned
    o4[t * 3 + 0] = make_float4(c[0], c[1], c[2], c[3]);
    o4[t * 3 + 1] = make_float4(c[4], c[5], c[6], c[7]);
    o4[t * 3 + 2] = make_float4(c[8], c[9], c[10], c[11]);

    // Restore empty sentinel (0) for the next replay.
    ulonglong2 zero = make_ulonglong2(0ULL, 0ULL);
    __stcs(&zb[t * 2 + 0], zero);
    __stcs(&zb[t * 2 + 1], zero);
}

extern "C" void kernel_launch(void* const* d_in, const int* in_sizes, int n_in,
                              void* d_out, int out_size) {
    const float* points = (const float*)d_in[0];
    const float* colors = (const float*)d_in[1];
    const float* Kmat   = (const float*)d_in[2];
    float* out = (float*)d_out;

    // 1) pack colors (plain launch)
    pack_kernel<<<(NPTS / 8 + 255) / 256, 256>>>(colors);

    cudaLaunchAttribute pdl_attr[1];
    pdl_attr[0].id = cudaLaunchAttributeProgrammaticStreamSerialization;
    pdl_attr[0].val.programmaticStreamSerializationAllowed = 1;

    // 2) project (PDL: point loads overlap pack; rgb loads + REDs after sync)
    {
        cudaLaunchConfig_t cfg = {};
        cfg.gridDim = dim3((NPTS / 8 + 255) / 256);  // 2048 CTAs
        cfg.blockDim = dim3(256);
        cfg.attrs = pdl_attr;
        cfg.numAttrs = 1;
        cudaLaunchKernelEx(&cfg, project_kernel, points, Kmat);
    }

    // 3) gather (PDL: ramp overlaps project tail; sync before reading zbuf)
    {
        cudaLaunchConfig_t cfg = {};
        cfg.gridDim = dim3((NPIX / 4 + 255) / 256);  // 1280 CTAs
        cfg.blockDim = dim3(256);
        cfg.attrs = pdl_attr;
        cfg.numAttrs = 1;
        cudaLaunchKernelEx(&cfg, gather_kernel, out);
    }
}